// round 1
// baseline (speedup 1.0000x reference)
#include <cuda_runtime.h>
#include <cstdint>

#define HDIM 2048
#define NROWS 8192

// Scratch (allocation-free rule: __device__ globals)
__device__ float g_y[(size_t)NROWS * HDIM];   // LN outputs (reused for LN1 and LN2)
__device__ float g_h[(size_t)NROWS * HDIM];   // GEMM1 output
__device__ float g_w[(size_t)HDIM * HDIM];    // tf32-rounded weights (reused)

__device__ __forceinline__ float tf32_rna(float x) {
    uint32_t u;
    asm("cvt.rna.tf32.f32 %0, %1;" : "=r"(u) : "f"(x));
    return __uint_as_float(u);
}

// ---------------------------------------------------------------------------
// LayerNorm: one block (256 threads) per row of 2048 floats.
// Output is tf32-rounded so the GEMM needs no CVT in its inner loop.
// ---------------------------------------------------------------------------
__global__ __launch_bounds__(256) void ln_kernel(
    const float* __restrict__ in, const float* __restrict__ gamma,
    const float* __restrict__ beta, float* __restrict__ out)
{
    const int row = blockIdx.x;
    const int t = threadIdx.x;
    const float4* inr = reinterpret_cast<const float4*>(in + (size_t)row * HDIM);
    float4 v0 = inr[t];
    float4 v1 = inr[t + 256];

    float s  = v0.x + v0.y + v0.z + v0.w + v1.x + v1.y + v1.z + v1.w;
    float ss = v0.x*v0.x + v0.y*v0.y + v0.z*v0.z + v0.w*v0.w
             + v1.x*v1.x + v1.y*v1.y + v1.z*v1.z + v1.w*v1.w;

    #pragma unroll
    for (int o = 16; o > 0; o >>= 1) {
        s  += __shfl_xor_sync(0xffffffffu, s, o);
        ss += __shfl_xor_sync(0xffffffffu, ss, o);
    }
    __shared__ float sh_s[8], sh_ss[8];
    if ((t & 31) == 0) { sh_s[t >> 5] = s; sh_ss[t >> 5] = ss; }
    __syncthreads();
    float tot = 0.f, tot2 = 0.f;
    #pragma unroll
    for (int i = 0; i < 8; i++) { tot += sh_s[i]; tot2 += sh_ss[i]; }

    const float mu  = tot * (1.0f / HDIM);
    const float var = tot2 * (1.0f / HDIM) - mu * mu;
    const float rs  = rsqrtf(var + 1e-5f);

    const float4* gr = reinterpret_cast<const float4*>(gamma);
    const float4* br = reinterpret_cast<const float4*>(beta);
    float4 ga = gr[t], gb = gr[t + 256];
    float4 ba = br[t], bb = br[t + 256];

    float4 o0, o1;
    o0.x = tf32_rna((v0.x - mu) * rs * ga.x + ba.x);
    o0.y = tf32_rna((v0.y - mu) * rs * ga.y + ba.y);
    o0.z = tf32_rna((v0.z - mu) * rs * ga.z + ba.z);
    o0.w = tf32_rna((v0.w - mu) * rs * ga.w + ba.w);
    o1.x = tf32_rna((v1.x - mu) * rs * gb.x + bb.x);
    o1.y = tf32_rna((v1.y - mu) * rs * gb.y + bb.y);
    o1.z = tf32_rna((v1.z - mu) * rs * gb.z + bb.z);
    o1.w = tf32_rna((v1.w - mu) * rs * gb.w + bb.w);

    float4* outr = reinterpret_cast<float4*>(out + (size_t)row * HDIM);
    outr[t] = o0;
    outr[t + 256] = o1;
}

// ---------------------------------------------------------------------------
// Round a weight matrix to tf32 (RNA) once, so GEMM inner loop has no CVTs.
// ---------------------------------------------------------------------------
__global__ __launch_bounds__(256) void cvt_tf32_kernel(
    const float* __restrict__ in, float* __restrict__ out, int n4)
{
    int i = blockIdx.x * blockDim.x + threadIdx.x;
    if (i < n4) {
        float4 v = reinterpret_cast<const float4*>(in)[i];
        v.x = tf32_rna(v.x); v.y = tf32_rna(v.y);
        v.z = tf32_rna(v.z); v.w = tf32_rna(v.w);
        reinterpret_cast<float4*>(out)[i] = v;
    }
}

// ---------------------------------------------------------------------------
// GEMM: C[M,N] = epilogue(A[M,K] @ B[N,K]^T + bias (+ resid)), ReLU.
// A row-major (K contiguous), B row-major [N,K] == col-major K x N -> row.col mma.
// Block tile 128x128x32, 8 warps (2x4) of 64x32, mma.sync m16n8k8 tf32,
// cp.async double buffering. Smem stride BK+4=36 (== 4 mod 32) makes both the
// A and B fragment LDS patterns (8 rows x 4 k's per warp) bank-conflict-free.
// ---------------------------------------------------------------------------
#define BM 128
#define BN 128
#define BK 32
#define LDT (BK + 4)                       // 36 floats
#define SMEM_FLOATS (2 * BM * LDT + 2 * BN * LDT)
#define SMEM_BYTES (SMEM_FLOATS * 4)       // 73728

extern __shared__ float gemm_smem[];

__global__ __launch_bounds__(256, 2) void gemm_tf32(
    const float* __restrict__ A, const float* __restrict__ B,
    const float* __restrict__ bias, const float* __restrict__ resid,
    float* __restrict__ C, int M, int N, int K)
{
    float* As = gemm_smem;                 // [2][BM][LDT]
    float* Bs = gemm_smem + 2 * BM * LDT;  // [2][BN][LDT]

    const int tid  = threadIdx.x;
    const int warp = tid >> 5, lane = tid & 31;
    const int wm = warp >> 2, wn = warp & 3;       // 2 x 4 warp grid
    const int gid = lane >> 2, tig = lane & 3;     // mma groupID / thread-in-group
    const int bm0 = blockIdx.y * BM;
    const int bn0 = blockIdx.x * BN;

    const float* Ag = A + (size_t)bm0 * K;
    const float* Bg = B + (size_t)bn0 * K;

    float acc[4][4][4];
    #pragma unroll
    for (int i = 0; i < 4; i++)
        #pragma unroll
        for (int j = 0; j < 4; j++)
            #pragma unroll
            for (int r = 0; r < 4; r++) acc[i][j][r] = 0.f;

    auto load_tile = [&](int kt, int st) {
        const int k0 = kt * BK;
        #pragma unroll
        for (int i = 0; i < 4; i++) {
            int idx = tid + i * 256;
            int r = idx >> 3, c = (idx & 7) * 4;
            uint32_t sa = (uint32_t)__cvta_generic_to_shared(&As[st * BM * LDT + r * LDT + c]);
            const float* gp = Ag + (size_t)r * K + k0 + c;
            asm volatile("cp.async.cg.shared.global [%0], [%1], 16;\n" :: "r"(sa), "l"(gp));
        }
        #pragma unroll
        for (int i = 0; i < 4; i++) {
            int idx = tid + i * 256;
            int r = idx >> 3, c = (idx & 7) * 4;
            uint32_t sb = (uint32_t)__cvta_generic_to_shared(&Bs[st * BN * LDT + r * LDT + c]);
            const float* gp = Bg + (size_t)r * K + k0 + c;
            asm volatile("cp.async.cg.shared.global [%0], [%1], 16;\n" :: "r"(sb), "l"(gp));
        }
        asm volatile("cp.async.commit_group;\n");
    };

    load_tile(0, 0);
    asm volatile("cp.async.wait_group 0;\n");
    __syncthreads();

    const int KT = K / BK;
    for (int kt = 0; kt < KT; kt++) {
        const int st = kt & 1;
        if (kt + 1 < KT) load_tile(kt + 1, st ^ 1);

        const float* Asb = As + st * BM * LDT + (wm * 64) * LDT;
        const float* Bsb = Bs + st * BN * LDT + (wn * 32) * LDT;

        #pragma unroll
        for (int ks = 0; ks < 4; ks++) {
            const int k0 = ks * 8;
            uint32_t a[4][4], bfr[4][2];
            #pragma unroll
            for (int fm = 0; fm < 4; fm++) {
                const float* p  = Asb + (fm * 16 + gid) * LDT + k0 + tig;
                const float* p2 = p + 8 * LDT;
                a[fm][0] = __float_as_uint(p[0]);
                a[fm][2] = __float_as_uint(p[4]);
                a[fm][1] = __float_as_uint(p2[0]);
                a[fm][3] = __float_as_uint(p2[4]);
            }
            #pragma unroll
            for (int fn = 0; fn < 4; fn++) {
                const float* p = Bsb + (fn * 8 + gid) * LDT + k0 + tig;
                bfr[fn][0] = __float_as_uint(p[0]);
                bfr[fn][1] = __float_as_uint(p[4]);
            }
            #pragma unroll
            for (int fm = 0; fm < 4; fm++)
                #pragma unroll
                for (int fn = 0; fn < 4; fn++) {
                    asm volatile(
                        "mma.sync.aligned.m16n8k8.row.col.f32.tf32.tf32.f32 "
                        "{%0,%1,%2,%3}, {%4,%5,%6,%7}, {%8,%9}, {%0,%1,%2,%3};\n"
                        : "+f"(acc[fm][fn][0]), "+f"(acc[fm][fn][1]),
                          "+f"(acc[fm][fn][2]), "+f"(acc[fm][fn][3])
                        : "r"(a[fm][0]), "r"(a[fm][1]), "r"(a[fm][2]), "r"(a[fm][3]),
                          "r"(bfr[fn][0]), "r"(bfr[fn][1]));
                }
        }
        asm volatile("cp.async.wait_group 0;\n");
        __syncthreads();
    }

    // Epilogue: + bias, (+ resid), ReLU
    #pragma unroll
    for (int fm = 0; fm < 4; fm++) {
        const int r0 = bm0 + wm * 64 + fm * 16 + gid;
        const int r1 = r0 + 8;
        #pragma unroll
        for (int fn = 0; fn < 4; fn++) {
            const int col = bn0 + wn * 32 + fn * 8 + 2 * tig;
            const float2 bv = *reinterpret_cast<const float2*>(bias + col);
            float o00 = acc[fm][fn][0] + bv.x;
            float o01 = acc[fm][fn][1] + bv.y;
            float o10 = acc[fm][fn][2] + bv.x;
            float o11 = acc[fm][fn][3] + bv.y;
            if (resid) {
                const float2 x0 = *reinterpret_cast<const float2*>(resid + (size_t)r0 * N + col);
                const float2 x1 = *reinterpret_cast<const float2*>(resid + (size_t)r1 * N + col);
                o00 += x0.x; o01 += x0.y; o10 += x1.x; o11 += x1.y;
            }
            o00 = fmaxf(o00, 0.f); o01 = fmaxf(o01, 0.f);
            o10 = fmaxf(o10, 0.f); o11 = fmaxf(o11, 0.f);
            *reinterpret_cast<float2*>(C + (size_t)r0 * N + col) = make_float2(o00, o01);
            *reinterpret_cast<float2*>(C + (size_t)r1 * N + col) = make_float2(o10, o11);
        }
    }
}

// ---------------------------------------------------------------------------
extern "C" void kernel_launch(void* const* d_in, const int* in_sizes, int n_in,
                              void* d_out, int out_size)
{
    const float* x   = (const float*)d_in[0];
    const float* W1  = (const float*)d_in[1];
    const float* b1  = (const float*)d_in[2];
    const float* W2  = (const float*)d_in[3];
    const float* b2  = (const float*)d_in[4];
    const float* g1  = (const float*)d_in[5];
    const float* be1 = (const float*)d_in[6];
    const float* g2  = (const float*)d_in[7];
    const float* be2 = (const float*)d_in[8];
    float* out = (float*)d_out;

    float *y, *h, *w;
    cudaGetSymbolAddress((void**)&y, g_y);
    cudaGetSymbolAddress((void**)&h, g_h);
    cudaGetSymbolAddress((void**)&w, g_w);

    cudaFuncSetAttribute(gemm_tf32, cudaFuncAttributeMaxDynamicSharedMemorySize, SMEM_BYTES);

    const int wn4 = HDIM * HDIM / 4;
    dim3 ggrid(HDIM / BN, NROWS / BM);

    // ln1 -> gemm1(relu,+b1) -> ln2 -> gemm2(+b2,+x,relu)
    ln_kernel<<<NROWS, 256>>>(x, g1, be1, y);
    cvt_tf32_kernel<<<(wn4 + 255) / 256, 256>>>(W1, w, wn4);
    gemm_tf32<<<ggrid, 256, SMEM_BYTES>>>(y, w, b1, nullptr, h, NROWS, HDIM, HDIM);
    ln_kernel<<<NROWS, 256>>>(h, g2, be2, y);
    cvt_tf32_kernel<<<(wn4 + 255) / 256, 256>>>(W2, w, wn4);
    gemm_tf32<<<ggrid, 256, SMEM_BYTES>>>(y, w, b2, x, out, NROWS, HDIM, HDIM);
}

// round 3
// speedup vs baseline: 1.3551x; 1.3551x over previous
#include <cuda_runtime.h>
#include <cstdint>

#define HDIM 2048
#define NROWS 8192

// Scratch (allocation-free rule: __device__ globals)
__device__ float g_y[(size_t)NROWS * HDIM];   // LN outputs (tf32-rounded)
__device__ float g_h[(size_t)NROWS * HDIM];   // GEMM1 output
__device__ float g_w[(size_t)HDIM * HDIM];    // tf32-rounded weights (reused)

__device__ __forceinline__ float tf32_rna(float x) {
    uint32_t u;
    asm("cvt.rna.tf32.f32 %0, %1;" : "=r"(u) : "f"(x));
    return __uint_as_float(u);
}

// ---------------------------------------------------------------------------
// LayerNorm: one block (256 threads) per row of 2048 floats, tf32-rounded out.
// ---------------------------------------------------------------------------
__global__ __launch_bounds__(256) void ln_kernel(
    const float* __restrict__ in, const float* __restrict__ gamma,
    const float* __restrict__ beta, float* __restrict__ out)
{
    const int row = blockIdx.x;
    const int t = threadIdx.x;
    const float4* inr = reinterpret_cast<const float4*>(in + (size_t)row * HDIM);
    float4 v0 = inr[t];
    float4 v1 = inr[t + 256];

    float s  = v0.x + v0.y + v0.z + v0.w + v1.x + v1.y + v1.z + v1.w;
    float ss = v0.x*v0.x + v0.y*v0.y + v0.z*v0.z + v0.w*v0.w
             + v1.x*v1.x + v1.y*v1.y + v1.z*v1.z + v1.w*v1.w;

    #pragma unroll
    for (int o = 16; o > 0; o >>= 1) {
        s  += __shfl_xor_sync(0xffffffffu, s, o);
        ss += __shfl_xor_sync(0xffffffffu, ss, o);
    }
    __shared__ float sh_s[8], sh_ss[8];
    if ((t & 31) == 0) { sh_s[t >> 5] = s; sh_ss[t >> 5] = ss; }
    __syncthreads();
    float tot = 0.f, tot2 = 0.f;
    #pragma unroll
    for (int i = 0; i < 8; i++) { tot += sh_s[i]; tot2 += sh_ss[i]; }

    const float mu  = tot * (1.0f / HDIM);
    const float var = tot2 * (1.0f / HDIM) - mu * mu;
    const float rs  = rsqrtf(var + 1e-5f);

    const float4* gr = reinterpret_cast<const float4*>(gamma);
    const float4* br = reinterpret_cast<const float4*>(beta);
    float4 ga = gr[t], gb = gr[t + 256];
    float4 ba = br[t], bb = br[t + 256];

    float4 o0, o1;
    o0.x = tf32_rna((v0.x - mu) * rs * ga.x + ba.x);
    o0.y = tf32_rna((v0.y - mu) * rs * ga.y + ba.y);
    o0.z = tf32_rna((v0.z - mu) * rs * ga.z + ba.z);
    o0.w = tf32_rna((v0.w - mu) * rs * ga.w + ba.w);
    o1.x = tf32_rna((v1.x - mu) * rs * gb.x + bb.x);
    o1.y = tf32_rna((v1.y - mu) * rs * gb.y + bb.y);
    o1.z = tf32_rna((v1.z - mu) * rs * gb.z + bb.z);
    o1.w = tf32_rna((v1.w - mu) * rs * gb.w + bb.w);

    float4* outr = reinterpret_cast<float4*>(out + (size_t)row * HDIM);
    outr[t] = o0;
    outr[t + 256] = o1;
}

// ---------------------------------------------------------------------------
// Round a weight matrix to tf32 (RNA) once.
// ---------------------------------------------------------------------------
__global__ __launch_bounds__(256) void cvt_tf32_kernel(
    const float* __restrict__ in, float* __restrict__ out, int n4)
{
    int i = blockIdx.x * blockDim.x + threadIdx.x;
    if (i < n4) {
        float4 v = reinterpret_cast<const float4*>(in)[i];
        v.x = tf32_rna(v.x); v.y = tf32_rna(v.y);
        v.z = tf32_rna(v.z); v.w = tf32_rna(v.w);
        reinterpret_cast<float4*>(out)[i] = v;
    }
}

// ---------------------------------------------------------------------------
// GEMM: C[M,N] = relu(A[M,K] @ B[N,K]^T + bias (+resid)).
// CTA tile 128x128x32, 4 warps of 64x64, mma.sync m16n8k8 tf32, fragments via
// ldmatrix.x4, 3-stage cp.async pipeline, SW128-swizzled smem.
// ---------------------------------------------------------------------------
#define BM 128
#define BN 128
#define BK 32
#define NSTAGE 3
#define KTILES (HDIM / BK)            // 64
#define STAGE_BYTES 16384             // 128 rows * 128B (A or B)
#define GEMM_SMEM (NSTAGE * 2 * STAGE_BYTES + 1024)

#define LDSM4(R0, R1, R2, R3, ADDR) \
    asm volatile("ldmatrix.sync.aligned.m8n8.x4.shared.b16 {%0,%1,%2,%3}, [%4];" \
        : "=r"(R0), "=r"(R1), "=r"(R2), "=r"(R3) : "r"(ADDR))

extern __shared__ char gsm[];

__global__ __launch_bounds__(128, 2) void gemm_tf32(
    const float* __restrict__ A, const float* __restrict__ B,
    const float* __restrict__ bias, const float* __restrict__ resid,
    float* __restrict__ C)
{
    const int K = HDIM, N = HDIM;
    const int tid  = threadIdx.x;
    const int warp = tid >> 5, lane = tid & 31;
    const int wm = warp >> 1, wn = warp & 1;       // 2x2 warps, 64x64 each
    const int gid = lane >> 2, tig = lane & 3;
    const int bm0 = blockIdx.y * BM;
    const int bn0 = blockIdx.x * BN;

    uint32_t sbase = (uint32_t)__cvta_generic_to_shared(gsm);
    sbase = (sbase + 1023) & ~1023u;
    const uint32_t aB = sbase;
    const uint32_t bB = sbase + NSTAGE * STAGE_BYTES;

    const float* Ag = A + (size_t)bm0 * K;
    const float* Bg = B + (size_t)bn0 * K;

    // cp.async: 2048 16B chunks per stage (A:1024 + B:1024), 128 threads -> 16 each
    auto load_stage = [&](int t) {
        const int s = t % NSTAGE;
        const int k0 = t * BK;
        #pragma unroll
        for (int i = 0; i < 8; i++) {
            int idx = tid + i * 128;
            int r = idx >> 3, c = idx & 7;
            uint32_t dst = aB + s * STAGE_BYTES + r * 128 + ((c ^ (r & 7)) << 4);
            const float* gp = Ag + (size_t)r * K + k0 + c * 4;
            asm volatile("cp.async.cg.shared.global [%0], [%1], 16;\n" :: "r"(dst), "l"(gp));
        }
        #pragma unroll
        for (int i = 0; i < 8; i++) {
            int idx = tid + i * 128;
            int r = idx >> 3, c = idx & 7;
            uint32_t dst = bB + s * STAGE_BYTES + r * 128 + ((c ^ (r & 7)) << 4);
            const float* gp = Bg + (size_t)r * K + k0 + c * 4;
            asm volatile("cp.async.cg.shared.global [%0], [%1], 16;\n" :: "r"(dst), "l"(gp));
        }
    };

    float acc[4][8][4];
    #pragma unroll
    for (int i = 0; i < 4; i++)
        #pragma unroll
        for (int j = 0; j < 8; j++)
            #pragma unroll
            for (int r = 0; r < 4; r++) acc[i][j][r] = 0.f;

    // ldmatrix per-thread address components
    // A x4 (16 rows x 8 k): lanes 0-7 rows0-7 kc, 8-15 rows8-15 kc, 16-23 rows0-7 kc+1, 24-31 rows8-15 kc+1
    const int aRow = wm * 64 + (lane & 15);
    const uint32_t aRowOff = (uint32_t)aRow * 128;
    const int aChOff = lane >> 4;
    // B x4 (16 n x 8 k): lanes 0-7 n0-7 kc, 8-15 n0-7 kc+1, 16-23 n8-15 kc, 24-31 n8-15 kc+1
    const int bRow = wn * 64 + ((lane & 7) | ((lane & 16) >> 1));
    const uint32_t bRowOff = (uint32_t)bRow * 128;
    const int bChOff = (lane >> 3) & 1;
    const int swz = lane & 7;  // row&7 for both (tile/fragment offsets are multiples of 8 rows)

    // Prologue: stages 0,1 in flight
    load_stage(0);
    asm volatile("cp.async.commit_group;\n");
    load_stage(1);
    asm volatile("cp.async.commit_group;\n");

    for (int kt = 0; kt < KTILES; kt++) {
        asm volatile("cp.async.wait_group 1;\n");
        __syncthreads();

        // Issue next load (stage being overwritten was last read at kt-1; barrier above protects it)
        if (kt + 2 < KTILES) load_stage(kt + 2);
        asm volatile("cp.async.commit_group;\n");

        const int s = kt % NSTAGE;
        const uint32_t aS = aB + s * STAGE_BYTES;
        const uint32_t bS = bB + s * STAGE_BYTES;

        #pragma unroll
        for (int ks = 0; ks < 4; ks++) {
            uint32_t ar[4][4], br[8][2];
            #pragma unroll
            for (int fm = 0; fm < 4; fm++) {
                uint32_t addr = aS + aRowOff + fm * 2048 + (uint32_t)(((2 * ks + aChOff) ^ swz) << 4);
                LDSM4(ar[fm][0], ar[fm][1], ar[fm][2], ar[fm][3], addr);
            }
            #pragma unroll
            for (int fb = 0; fb < 4; fb++) {
                uint32_t addr = bS + bRowOff + fb * 2048 + (uint32_t)(((2 * ks + bChOff) ^ swz) << 4);
                LDSM4(br[2*fb][0], br[2*fb][1], br[2*fb+1][0], br[2*fb+1][1], addr);
            }
            #pragma unroll
            for (int fm = 0; fm < 4; fm++)
                #pragma unroll
                for (int fn = 0; fn < 8; fn++) {
                    asm volatile(
                        "mma.sync.aligned.m16n8k8.row.col.f32.tf32.tf32.f32 "
                        "{%0,%1,%2,%3}, {%4,%5,%6,%7}, {%8,%9}, {%0,%1,%2,%3};\n"
                        : "+f"(acc[fm][fn][0]), "+f"(acc[fm][fn][1]),
                          "+f"(acc[fm][fn][2]), "+f"(acc[fm][fn][3])
                        : "r"(ar[fm][0]), "r"(ar[fm][1]), "r"(ar[fm][2]), "r"(ar[fm][3]),
                          "r"(br[fn][0]), "r"(br[fn][1]));
                }
        }
        __syncthreads();
    }

    // Epilogue: + bias, (+ resid), ReLU
    #pragma unroll
    for (int fm = 0; fm < 4; fm++) {
        const int r0 = bm0 + wm * 64 + fm * 16 + gid;
        const int r1 = r0 + 8;
        #pragma unroll
        for (int fn = 0; fn < 8; fn++) {
            const int col = bn0 + wn * 64 + fn * 8 + 2 * tig;
            const float2 bv = *reinterpret_cast<const float2*>(bias + col);
            float o00 = acc[fm][fn][0] + bv.x;
            float o01 = acc[fm][fn][1] + bv.y;
            float o10 = acc[fm][fn][2] + bv.x;
            float o11 = acc[fm][fn][3] + bv.y;
            if (resid) {
                const float2 x0 = *reinterpret_cast<const float2*>(resid + (size_t)r0 * N + col);
                const float2 x1 = *reinterpret_cast<const float2*>(resid + (size_t)r1 * N + col);
                o00 += x0.x; o01 += x0.y; o10 += x1.x; o11 += x1.y;
            }
            o00 = fmaxf(o00, 0.f); o01 = fmaxf(o01, 0.f);
            o10 = fmaxf(o10, 0.f); o11 = fmaxf(o11, 0.f);
            *reinterpret_cast<float2*>(C + (size_t)r0 * N + col) = make_float2(o00, o01);
            *reinterpret_cast<float2*>(C + (size_t)r1 * N + col) = make_float2(o10, o11);
        }
    }
}

// ---------------------------------------------------------------------------
extern "C" void kernel_launch(void* const* d_in, const int* in_sizes, int n_in,
                              void* d_out, int out_size)
{
    const float* x   = (const float*)d_in[0];
    const float* W1  = (const float*)d_in[1];
    const float* b1  = (const float*)d_in[2];
    const float* W2  = (const float*)d_in[3];
    const float* b2  = (const float*)d_in[4];
    const float* g1  = (const float*)d_in[5];
    const float* be1 = (const float*)d_in[6];
    const float* g2  = (const float*)d_in[7];
    const float* be2 = (const float*)d_in[8];
    float* out = (float*)d_out;

    float *y, *h, *w;
    cudaGetSymbolAddress((void**)&y, g_y);
    cudaGetSymbolAddress((void**)&h, g_h);
    cudaGetSymbolAddress((void**)&w, g_w);

    cudaFuncSetAttribute(gemm_tf32, cudaFuncAttributeMaxDynamicSharedMemorySize, GEMM_SMEM);

    const int wn4 = HDIM * HDIM / 4;
    dim3 ggrid(HDIM / BN, NROWS / BM);   // (16, 64)

    ln_kernel<<<NROWS, 256>>>(x, g1, be1, y);
    cvt_tf32_kernel<<<(wn4 + 255) / 256, 256>>>(W1, w, wn4);
    gemm_tf32<<<ggrid, 128, GEMM_SMEM>>>(y, w, b1, nullptr, h);
    ln_kernel<<<NROWS, 256>>>(h, g2, be2, y);
    cvt_tf32_kernel<<<(wn4 + 255) / 256, 256>>>(W2, w, wn4);
    gemm_tf32<<<ggrid, 128, GEMM_SMEM>>>(y, w, b2, x, out);
}

// round 4
// speedup vs baseline: 1.3987x; 1.0322x over previous
#include <cuda_runtime.h>
#include <cstdint>

#define HDIM 2048
#define NROWS 8192

// Scratch (allocation-free rule: __device__ globals)
__device__ float g_y[(size_t)NROWS * HDIM];   // LN outputs (tf32-rounded)
__device__ float g_h[(size_t)NROWS * HDIM];   // GEMM1 output
__device__ float g_w1[(size_t)HDIM * HDIM];   // tf32-rounded W1
__device__ float g_w2[(size_t)HDIM * HDIM];   // tf32-rounded W2

__device__ __forceinline__ float tf32_rna(float x) {
    uint32_t u;
    asm("cvt.rna.tf32.f32 %0, %1;" : "=r"(u) : "f"(x));
    return __uint_as_float(u);
}

// ---------------------------------------------------------------------------
// LayerNorm: one block (256 threads) per row of 2048 floats, tf32-rounded out.
// ---------------------------------------------------------------------------
__global__ __launch_bounds__(256) void ln_kernel(
    const float* __restrict__ in, const float* __restrict__ gamma,
    const float* __restrict__ beta, float* __restrict__ out)
{
    const int row = blockIdx.x;
    const int t = threadIdx.x;
    const float4* inr = reinterpret_cast<const float4*>(in + (size_t)row * HDIM);
    float4 v0 = inr[t];
    float4 v1 = inr[t + 256];

    float s  = v0.x + v0.y + v0.z + v0.w + v1.x + v1.y + v1.z + v1.w;
    float ss = v0.x*v0.x + v0.y*v0.y + v0.z*v0.z + v0.w*v0.w
             + v1.x*v1.x + v1.y*v1.y + v1.z*v1.z + v1.w*v1.w;

    #pragma unroll
    for (int o = 16; o > 0; o >>= 1) {
        s  += __shfl_xor_sync(0xffffffffu, s, o);
        ss += __shfl_xor_sync(0xffffffffu, ss, o);
    }
    __shared__ float sh_s[8], sh_ss[8];
    if ((t & 31) == 0) { sh_s[t >> 5] = s; sh_ss[t >> 5] = ss; }
    __syncthreads();
    float tot = 0.f, tot2 = 0.f;
    #pragma unroll
    for (int i = 0; i < 8; i++) { tot += sh_s[i]; tot2 += sh_ss[i]; }

    const float mu  = tot * (1.0f / HDIM);
    const float var = tot2 * (1.0f / HDIM) - mu * mu;
    const float rs  = rsqrtf(var + 1e-5f);

    const float4* gr = reinterpret_cast<const float4*>(gamma);
    const float4* br = reinterpret_cast<const float4*>(beta);
    float4 ga = gr[t], gb = gr[t + 256];
    float4 ba = br[t], bb = br[t + 256];

    float4 o0, o1;
    o0.x = tf32_rna((v0.x - mu) * rs * ga.x + ba.x);
    o0.y = tf32_rna((v0.y - mu) * rs * ga.y + ba.y);
    o0.z = tf32_rna((v0.z - mu) * rs * ga.z + ba.z);
    o0.w = tf32_rna((v0.w - mu) * rs * ga.w + ba.w);
    o1.x = tf32_rna((v1.x - mu) * rs * gb.x + bb.x);
    o1.y = tf32_rna((v1.y - mu) * rs * gb.y + bb.y);
    o1.z = tf32_rna((v1.z - mu) * rs * gb.z + bb.z);
    o1.w = tf32_rna((v1.w - mu) * rs * gb.w + bb.w);

    float4* outr = reinterpret_cast<float4*>(out + (size_t)row * HDIM);
    outr[t] = o0;
    outr[t + 256] = o1;
}

// ---------------------------------------------------------------------------
// Round both weight matrices to tf32 (RNA) in one launch.
// ---------------------------------------------------------------------------
__global__ __launch_bounds__(256) void cvt2_tf32_kernel(
    const float* __restrict__ in1, float* __restrict__ out1,
    const float* __restrict__ in2, float* __restrict__ out2, int n4)
{
    int i = blockIdx.x * blockDim.x + threadIdx.x;
    const float* in  = (i < n4) ? in1  : in2;
    float*       out = (i < n4) ? out1 : out2;
    int j = (i < n4) ? i : (i - n4);
    float4 v = reinterpret_cast<const float4*>(in)[j];
    v.x = tf32_rna(v.x); v.y = tf32_rna(v.y);
    v.z = tf32_rna(v.z); v.w = tf32_rna(v.w);
    reinterpret_cast<float4*>(out)[j] = v;
}

// ---------------------------------------------------------------------------
// GEMM: C[M,N] = relu(A[M,K] @ B[N,K]^T + bias (+resid)).
// CTA tile 128x128x32, 4 warps of 64x64, mma.sync m16n8k8 tf32, ldmatrix.x4
// fragments (register double-buffered), 3-stage cp.async, SW128 swizzle,
// single __syncthreads per k-tile.
// ---------------------------------------------------------------------------
#define BM 128
#define BN 128
#define BK 32
#define NSTAGE 3
#define KTILES (HDIM / BK)            // 64
#define STAGE_BYTES 16384             // 128 rows * 128B (A or B)
#define GEMM_SMEM (NSTAGE * 2 * STAGE_BYTES + 1024)

#define LDSM4(R0, R1, R2, R3, ADDR) \
    asm volatile("ldmatrix.sync.aligned.m8n8.x4.shared.b16 {%0,%1,%2,%3}, [%4];" \
        : "=r"(R0), "=r"(R1), "=r"(R2), "=r"(R3) : "r"(ADDR))

extern __shared__ char gsm[];

__global__ __launch_bounds__(128, 2) void gemm_tf32(
    const float* __restrict__ A, const float* __restrict__ B,
    const float* __restrict__ bias, const float* __restrict__ resid,
    float* __restrict__ C)
{
    const int K = HDIM, N = HDIM;
    const int tid  = threadIdx.x;
    const int warp = tid >> 5, lane = tid & 31;
    const int wm = warp >> 1, wn = warp & 1;       // 2x2 warps, 64x64 each
    const int gid = lane >> 2, tig = lane & 3;
    const int bm0 = blockIdx.y * BM;
    const int bn0 = blockIdx.x * BN;

    uint32_t sbase = (uint32_t)__cvta_generic_to_shared(gsm);
    sbase = (sbase + 1023) & ~1023u;
    const uint32_t aB = sbase;
    const uint32_t bB = sbase + NSTAGE * STAGE_BYTES;

    const float* Ag = A + (size_t)bm0 * K;
    const float* Bg = B + (size_t)bn0 * K;

    auto load_stage = [&](int t) {
        const int s = t % NSTAGE;
        const int k0 = t * BK;
        #pragma unroll
        for (int i = 0; i < 8; i++) {
            int idx = tid + i * 128;
            int r = idx >> 3, c = idx & 7;
            uint32_t dst = aB + s * STAGE_BYTES + r * 128 + ((c ^ (r & 7)) << 4);
            const float* gp = Ag + (size_t)r * K + k0 + c * 4;
            asm volatile("cp.async.cg.shared.global [%0], [%1], 16;\n" :: "r"(dst), "l"(gp));
        }
        #pragma unroll
        for (int i = 0; i < 8; i++) {
            int idx = tid + i * 128;
            int r = idx >> 3, c = idx & 7;
            uint32_t dst = bB + s * STAGE_BYTES + r * 128 + ((c ^ (r & 7)) << 4);
            const float* gp = Bg + (size_t)r * K + k0 + c * 4;
            asm volatile("cp.async.cg.shared.global [%0], [%1], 16;\n" :: "r"(dst), "l"(gp));
        }
    };

    float acc[4][8][4];
    #pragma unroll
    for (int i = 0; i < 4; i++)
        #pragma unroll
        for (int j = 0; j < 8; j++)
            #pragma unroll
            for (int r = 0; r < 4; r++) acc[i][j][r] = 0.f;

    // ldmatrix per-thread address components (SW128 swizzle: chunk ^ (row&7))
    const int aRow = wm * 64 + (lane & 15);
    const uint32_t aRowOff = (uint32_t)aRow * 128;
    const int aChOff = lane >> 4;
    const int bRow = wn * 64 + ((lane & 7) | ((lane & 16) >> 1));
    const uint32_t bRowOff = (uint32_t)bRow * 128;
    const int bChOff = (lane >> 3) & 1;
    const int swz = lane & 7;

    uint32_t ar[2][4][4], br[2][8][2];

    auto load_frags = [&](uint32_t aS, uint32_t bS, int ks, int buf) {
        #pragma unroll
        for (int fm = 0; fm < 4; fm++) {
            uint32_t addr = aS + aRowOff + fm * 2048 + (uint32_t)(((2 * ks + aChOff) ^ swz) << 4);
            LDSM4(ar[buf][fm][0], ar[buf][fm][1], ar[buf][fm][2], ar[buf][fm][3], addr);
        }
        #pragma unroll
        for (int fb = 0; fb < 4; fb++) {
            uint32_t addr = bS + bRowOff + fb * 2048 + (uint32_t)(((2 * ks + bChOff) ^ swz) << 4);
            LDSM4(br[buf][2*fb][0], br[buf][2*fb][1], br[buf][2*fb+1][0], br[buf][2*fb+1][1], addr);
        }
    };

    // Prologue: stages 0,1 in flight
    load_stage(0);
    asm volatile("cp.async.commit_group;\n");
    load_stage(1);
    asm volatile("cp.async.commit_group;\n");

    for (int kt = 0; kt < KTILES; kt++) {
        asm volatile("cp.async.wait_group 1;\n");
        __syncthreads();

        const int s = kt % NSTAGE;
        const uint32_t aS = aB + s * STAGE_BYTES;
        const uint32_t bS = bB + s * STAGE_BYTES;

        // First fragment load, then overlap next-stage cp.async issue with math
        load_frags(aS, bS, 0, 0);
        if (kt + 2 < KTILES) load_stage(kt + 2);
        asm volatile("cp.async.commit_group;\n");

        #pragma unroll
        for (int ks = 0; ks < 4; ks++) {
            const int cur = ks & 1;
            if (ks < 3) load_frags(aS, bS, ks + 1, cur ^ 1);
            #pragma unroll
            for (int fm = 0; fm < 4; fm++)
                #pragma unroll
                for (int fn = 0; fn < 8; fn++) {
                    asm volatile(
                        "mma.sync.aligned.m16n8k8.row.col.f32.tf32.tf32.f32 "
                        "{%0,%1,%2,%3}, {%4,%5,%6,%7}, {%8,%9}, {%0,%1,%2,%3};\n"
                        : "+f"(acc[fm][fn][0]), "+f"(acc[fm][fn][1]),
                          "+f"(acc[fm][fn][2]), "+f"(acc[fm][fn][3])
                        : "r"(ar[cur][fm][0]), "r"(ar[cur][fm][1]),
                          "r"(ar[cur][fm][2]), "r"(ar[cur][fm][3]),
                          "r"(br[cur][fn][0]), "r"(br[cur][fn][1]));
                }
        }
    }

    // Epilogue: + bias, (+ resid), ReLU
    #pragma unroll
    for (int fm = 0; fm < 4; fm++) {
        const int r0 = bm0 + wm * 64 + fm * 16 + gid;
        const int r1 = r0 + 8;
        #pragma unroll
        for (int fn = 0; fn < 8; fn++) {
            const int col = bn0 + wn * 64 + fn * 8 + 2 * tig;
            const float2 bv = *reinterpret_cast<const float2*>(bias + col);
            float o00 = acc[fm][fn][0] + bv.x;
            float o01 = acc[fm][fn][1] + bv.y;
            float o10 = acc[fm][fn][2] + bv.x;
            float o11 = acc[fm][fn][3] + bv.y;
            if (resid) {
                const float2 x0 = *reinterpret_cast<const float2*>(resid + (size_t)r0 * N + col);
                const float2 x1 = *reinterpret_cast<const float2*>(resid + (size_t)r1 * N + col);
                o00 += x0.x; o01 += x0.y; o10 += x1.x; o11 += x1.y;
            }
            o00 = fmaxf(o00, 0.f); o01 = fmaxf(o01, 0.f);
            o10 = fmaxf(o10, 0.f); o11 = fmaxf(o11, 0.f);
            *reinterpret_cast<float2*>(C + (size_t)r0 * N + col) = make_float2(o00, o01);
            *reinterpret_cast<float2*>(C + (size_t)r1 * N + col) = make_float2(o10, o11);
        }
    }
}

// ---------------------------------------------------------------------------
extern "C" void kernel_launch(void* const* d_in, const int* in_sizes, int n_in,
                              void* d_out, int out_size)
{
    const float* x   = (const float*)d_in[0];
    const float* W1  = (const float*)d_in[1];
    const float* b1  = (const float*)d_in[2];
    const float* W2  = (const float*)d_in[3];
    const float* b2  = (const float*)d_in[4];
    const float* g1  = (const float*)d_in[5];
    const float* be1 = (const float*)d_in[6];
    const float* g2  = (const float*)d_in[7];
    const float* be2 = (const float*)d_in[8];
    float* out = (float*)d_out;

    float *y, *h, *w1, *w2;
    cudaGetSymbolAddress((void**)&y, g_y);
    cudaGetSymbolAddress((void**)&h, g_h);
    cudaGetSymbolAddress((void**)&w1, g_w1);
    cudaGetSymbolAddress((void**)&w2, g_w2);

    cudaFuncSetAttribute(gemm_tf32, cudaFuncAttributeMaxDynamicSharedMemorySize, GEMM_SMEM);

    const int wn4 = HDIM * HDIM / 4;
    dim3 ggrid(HDIM / BN, NROWS / BM);   // (16, 64)

    cvt2_tf32_kernel<<<(2 * wn4) / 256, 256>>>(W1, w1, W2, w2, wn4);
    ln_kernel<<<NROWS, 256>>>(x, g1, be1, y);
    gemm_tf32<<<ggrid, 128, GEMM_SMEM>>>(y, w1, b1, nullptr, h);
    ln_kernel<<<NROWS, 256>>>(h, g2, be2, y);
    gemm_tf32<<<ggrid, 128, GEMM_SMEM>>>(y, w2, b2, x, out);
}

// round 6
// speedup vs baseline: 2.4995x; 1.7871x over previous
#include <cuda_runtime.h>
#include <cuda_fp16.h>
#include <cstdint>
#include <cstring>

#define HDIM 2048
#define NROWS 8192

// Scratch (allocation-free rule: __device__ globals)
__device__ __half g_y[(size_t)NROWS * HDIM];   // LN outputs (fp16)
__device__ float  g_h[(size_t)NROWS * HDIM];   // GEMM1 output (fp32)
__device__ __half g_w1[(size_t)HDIM * HDIM];   // fp16 W1
__device__ __half g_w2[(size_t)HDIM * HDIM];   // fp16 W2

__device__ __forceinline__ uint32_t h2_bits(__half2 h) {
    uint32_t u;
    memcpy(&u, &h, 4);
    return u;
}

// ---------------------------------------------------------------------------
// LayerNorm: one block (256 threads) per row of 2048 floats -> fp16 out.
// ---------------------------------------------------------------------------
__global__ __launch_bounds__(256) void ln_kernel(
    const float* __restrict__ in, const float* __restrict__ gamma,
    const float* __restrict__ beta, __half* __restrict__ out)
{
    const int row = blockIdx.x;
    const int t = threadIdx.x;
    const float4* inr = reinterpret_cast<const float4*>(in + (size_t)row * HDIM);
    float4 v0 = inr[t];
    float4 v1 = inr[t + 256];

    float s  = v0.x + v0.y + v0.z + v0.w + v1.x + v1.y + v1.z + v1.w;
    float ss = v0.x*v0.x + v0.y*v0.y + v0.z*v0.z + v0.w*v0.w
             + v1.x*v1.x + v1.y*v1.y + v1.z*v1.z + v1.w*v1.w;

    #pragma unroll
    for (int o = 16; o > 0; o >>= 1) {
        s  += __shfl_xor_sync(0xffffffffu, s, o);
        ss += __shfl_xor_sync(0xffffffffu, ss, o);
    }
    __shared__ float sh_s[8], sh_ss[8];
    if ((t & 31) == 0) { sh_s[t >> 5] = s; sh_ss[t >> 5] = ss; }
    __syncthreads();
    float tot = 0.f, tot2 = 0.f;
    #pragma unroll
    for (int i = 0; i < 8; i++) { tot += sh_s[i]; tot2 += sh_ss[i]; }

    const float mu  = tot * (1.0f / HDIM);
    const float var = tot2 * (1.0f / HDIM) - mu * mu;
    const float rs  = rsqrtf(var + 1e-5f);

    const float4* gr = reinterpret_cast<const float4*>(gamma);
    const float4* br = reinterpret_cast<const float4*>(beta);
    float4 ga = gr[t], gb = gr[t + 256];
    float4 ba = br[t], bb = br[t + 256];

    __half2 h0 = __floats2half2_rn((v0.x - mu) * rs * ga.x + ba.x,
                                   (v0.y - mu) * rs * ga.y + ba.y);
    __half2 h1 = __floats2half2_rn((v0.z - mu) * rs * ga.z + ba.z,
                                   (v0.w - mu) * rs * ga.w + ba.w);
    __half2 h2 = __floats2half2_rn((v1.x - mu) * rs * gb.x + bb.x,
                                   (v1.y - mu) * rs * gb.y + bb.y);
    __half2 h3 = __floats2half2_rn((v1.z - mu) * rs * gb.z + bb.z,
                                   (v1.w - mu) * rs * gb.w + bb.w);

    // Row layout matches input: halves [4t,4t+4) and [4(t+256), +4).
    uint2* outr = reinterpret_cast<uint2*>(out + (size_t)row * HDIM);
    outr[t]       = make_uint2(h2_bits(h0), h2_bits(h1));
    outr[t + 256] = make_uint2(h2_bits(h2), h2_bits(h3));
}

// ---------------------------------------------------------------------------
// Convert both weight matrices to fp16 in one launch.
// ---------------------------------------------------------------------------
__global__ __launch_bounds__(256) void cvt2_f16_kernel(
    const float* __restrict__ in1, __half* __restrict__ out1,
    const float* __restrict__ in2, __half* __restrict__ out2, int n4)
{
    int i = blockIdx.x * blockDim.x + threadIdx.x;
    const float* in  = (i < n4) ? in1  : in2;
    __half*      out = (i < n4) ? out1 : out2;
    int j = (i < n4) ? i : (i - n4);
    float4 v = reinterpret_cast<const float4*>(in)[j];
    __half2 a = __floats2half2_rn(v.x, v.y);
    __half2 b = __floats2half2_rn(v.z, v.w);
    reinterpret_cast<uint2*>(out)[j] = make_uint2(h2_bits(a), h2_bits(b));
}

// ---------------------------------------------------------------------------
// GEMM: C[M,N] = relu(A[M,K] @ B[N,K]^T + bias (+resid)), fp16 operands,
// fp32 accumulate. CTA tile 128x128x64(halves), 4 warps of 64x64,
// mma.sync.m16n8k16.f16, ldmatrix.x4 (reg double-buffered), 3-stage cp.async,
// SW128 swizzle (128B rows = 64 halves), one __syncthreads per k-tile.
// ---------------------------------------------------------------------------
#define BM 128
#define BN 128
#define BKH 64                        // halves per k-tile (128 bytes)
#define NSTAGE 3
#define KTILES (HDIM / BKH)           // 32
#define STAGE_BYTES 16384             // 128 rows * 128B (A or B)
#define GEMM_SMEM (NSTAGE * 2 * STAGE_BYTES + 1024)

#define LDSM4(R0, R1, R2, R3, ADDR) \
    asm volatile("ldmatrix.sync.aligned.m8n8.x4.shared.b16 {%0,%1,%2,%3}, [%4];" \
        : "=r"(R0), "=r"(R1), "=r"(R2), "=r"(R3) : "r"(ADDR))

extern __shared__ char gsm[];

__global__ __launch_bounds__(128, 2) void gemm_f16(
    const __half* __restrict__ A, const __half* __restrict__ B,
    const float* __restrict__ bias, const float* __restrict__ resid,
    float* __restrict__ C)
{
    const int K = HDIM, N = HDIM;
    const int tid  = threadIdx.x;
    const int warp = tid >> 5, lane = tid & 31;
    const int wm = warp >> 1, wn = warp & 1;       // 2x2 warps, 64x64 each
    const int gid = lane >> 2, tig = lane & 3;
    const int bm0 = blockIdx.y * BM;
    const int bn0 = blockIdx.x * BN;

    uint32_t sbase = (uint32_t)__cvta_generic_to_shared(gsm);
    sbase = (sbase + 1023) & ~1023u;
    const uint32_t aB = sbase;
    const uint32_t bB = sbase + NSTAGE * STAGE_BYTES;

    const __half* Ag = A + (size_t)bm0 * K;
    const __half* Bg = B + (size_t)bn0 * K;

    auto load_stage = [&](int t) {
        const int s = t % NSTAGE;
        const int k0 = t * BKH;
        #pragma unroll
        for (int i = 0; i < 8; i++) {
            int idx = tid + i * 128;
            int r = idx >> 3, c = idx & 7;          // 8 chunks of 16B = 8 halves each
            uint32_t dst = aB + s * STAGE_BYTES + r * 128 + ((c ^ (r & 7)) << 4);
            const __half* gp = Ag + (size_t)r * K + k0 + c * 8;
            asm volatile("cp.async.cg.shared.global [%0], [%1], 16;\n" :: "r"(dst), "l"(gp));
        }
        #pragma unroll
        for (int i = 0; i < 8; i++) {
            int idx = tid + i * 128;
            int r = idx >> 3, c = idx & 7;
            uint32_t dst = bB + s * STAGE_BYTES + r * 128 + ((c ^ (r & 7)) << 4);
            const __half* gp = Bg + (size_t)r * K + k0 + c * 8;
            asm volatile("cp.async.cg.shared.global [%0], [%1], 16;\n" :: "r"(dst), "l"(gp));
        }
    };

    float acc[4][8][4];
    #pragma unroll
    for (int i = 0; i < 4; i++)
        #pragma unroll
        for (int j = 0; j < 8; j++)
            #pragma unroll
            for (int r = 0; r < 4; r++) acc[i][j][r] = 0.f;

    // ldmatrix addressing (byte-identical layout to the verified tf32 kernel).
    const int aRow = wm * 64 + (lane & 15);
    const uint32_t aRowOff = (uint32_t)aRow * 128;
    const int aChOff = lane >> 4;
    const int bRow = wn * 64 + ((lane & 7) | ((lane & 16) >> 1));
    const uint32_t bRowOff = (uint32_t)bRow * 128;
    const int bChOff = (lane >> 3) & 1;
    const int swz = lane & 7;

    uint32_t ar[2][4][4], br[2][8][2];

    auto load_frags = [&](uint32_t aS, uint32_t bS, int ks, int buf) {
        #pragma unroll
        for (int fm = 0; fm < 4; fm++) {
            uint32_t addr = aS + aRowOff + fm * 2048 + (uint32_t)(((2 * ks + aChOff) ^ swz) << 4);
            LDSM4(ar[buf][fm][0], ar[buf][fm][1], ar[buf][fm][2], ar[buf][fm][3], addr);
        }
        #pragma unroll
        for (int fb = 0; fb < 4; fb++) {
            uint32_t addr = bS + bRowOff + fb * 2048 + (uint32_t)(((2 * ks + bChOff) ^ swz) << 4);
            LDSM4(br[buf][2*fb][0], br[buf][2*fb][1], br[buf][2*fb+1][0], br[buf][2*fb+1][1], addr);
        }
    };

    // Prologue: stages 0,1 in flight
    load_stage(0);
    asm volatile("cp.async.commit_group;\n");
    load_stage(1);
    asm volatile("cp.async.commit_group;\n");

    for (int kt = 0; kt < KTILES; kt++) {
        asm volatile("cp.async.wait_group 1;\n");
        __syncthreads();

        const int s = kt % NSTAGE;
        const uint32_t aS = aB + s * STAGE_BYTES;
        const uint32_t bS = bB + s * STAGE_BYTES;

        load_frags(aS, bS, 0, 0);
        if (kt + 2 < KTILES) load_stage(kt + 2);
        asm volatile("cp.async.commit_group;\n");

        #pragma unroll
        for (int ks = 0; ks < 4; ks++) {            // 4 x k16 = 64 halves
            const int cur = ks & 1;
            if (ks < 3) load_frags(aS, bS, ks + 1, cur ^ 1);
            #pragma unroll
            for (int fm = 0; fm < 4; fm++)
                #pragma unroll
                for (int fn = 0; fn < 8; fn++) {
                    asm volatile(
                        "mma.sync.aligned.m16n8k16.row.col.f32.f16.f16.f32 "
                        "{%0,%1,%2,%3}, {%4,%5,%6,%7}, {%8,%9}, {%0,%1,%2,%3};\n"
                        : "+f"(acc[fm][fn][0]), "+f"(acc[fm][fn][1]),
                          "+f"(acc[fm][fn][2]), "+f"(acc[fm][fn][3])
                        : "r"(ar[cur][fm][0]), "r"(ar[cur][fm][1]),
                          "r"(ar[cur][fm][2]), "r"(ar[cur][fm][3]),
                          "r"(br[cur][fn][0]), "r"(br[cur][fn][1]));
                }
        }
    }

    // Epilogue: + bias, (+ resid), ReLU
    #pragma unroll
    for (int fm = 0; fm < 4; fm++) {
        const int r0 = bm0 + wm * 64 + fm * 16 + gid;
        const int r1 = r0 + 8;
        #pragma unroll
        for (int fn = 0; fn < 8; fn++) {
            const int col = bn0 + wn * 64 + fn * 8 + 2 * tig;
            const float2 bv = *reinterpret_cast<const float2*>(bias + col);
            float o00 = acc[fm][fn][0] + bv.x;
            float o01 = acc[fm][fn][1] + bv.y;
            float o10 = acc[fm][fn][2] + bv.x;
            float o11 = acc[fm][fn][3] + bv.y;
            if (resid) {
                const float2 x0 = *reinterpret_cast<const float2*>(resid + (size_t)r0 * N + col);
                const float2 x1 = *reinterpret_cast<const float2*>(resid + (size_t)r1 * N + col);
                o00 += x0.x; o01 += x0.y; o10 += x1.x; o11 += x1.y;
            }
            o00 = fmaxf(o00, 0.f); o01 = fmaxf(o01, 0.f);
            o10 = fmaxf(o10, 0.f); o11 = fmaxf(o11, 0.f);
            *reinterpret_cast<float2*>(C + (size_t)r0 * N + col) = make_float2(o00, o01);
            *reinterpret_cast<float2*>(C + (size_t)r1 * N + col) = make_float2(o10, o11);
        }
    }
}

// ---------------------------------------------------------------------------
extern "C" void kernel_launch(void* const* d_in, const int* in_sizes, int n_in,
                              void* d_out, int out_size)
{
    const float* x   = (const float*)d_in[0];
    const float* W1  = (const float*)d_in[1];
    const float* b1  = (const float*)d_in[2];
    const float* W2  = (const float*)d_in[3];
    const float* b2  = (const float*)d_in[4];
    const float* g1  = (const float*)d_in[5];
    const float* be1 = (const float*)d_in[6];
    const float* g2  = (const float*)d_in[7];
    const float* be2 = (const float*)d_in[8];
    float* out = (float*)d_out;

    __half *y, *w1, *w2;
    float *h;
    cudaGetSymbolAddress((void**)&y, g_y);
    cudaGetSymbolAddress((void**)&h, g_h);
    cudaGetSymbolAddress((void**)&w1, g_w1);
    cudaGetSymbolAddress((void**)&w2, g_w2);

    cudaFuncSetAttribute(gemm_f16, cudaFuncAttributeMaxDynamicSharedMemorySize, GEMM_SMEM);

    const int wn4 = HDIM * HDIM / 4;
    dim3 ggrid(HDIM / BN, NROWS / BM);   // (16, 64)

    cvt2_f16_kernel<<<(2 * wn4) / 256, 256>>>(W1, w1, W2, w2, wn4);
    ln_kernel<<<NROWS, 256>>>(x, g1, be1, y);
    gemm_f16<<<ggrid, 128, GEMM_SMEM>>>(y, w1, b1, nullptr, h);
    ln_kernel<<<NROWS, 256>>>(h, g2, be2, y);
    gemm_f16<<<ggrid, 128, GEMM_SMEM>>>(y, w2, b2, x, out);
}